// round 14
// baseline (speedup 1.0000x reference)
#include <cuda_runtime.h>
#include <cuda_bf16.h>
#include <cstdint>
#include <math.h>

// ============================================================
// bf16-split GEMM per layer via mma.sync (HMMA).
//   layer i: out[c,j] = tanh( sum_k W[c,k]*B[k,j] + bias[c] )
//   B[k][j] = in[k>>1][2j + (k&1)]   (compacted dilated conv)
//   fp32 ~= bf16 hi+lo:  A*B ~= Ah*Bh + Ah*Bl + Al*Bh
// R14: R13 +
//   - NT64 warp grid 4Mx2N (A-dup x2 instead of x4: -20% ldsm)
//   - split-K reduce fused into GEMM epilogue (last-CTA-done)
//   - layer 2 runs NT128 with S=2
// ============================================================

#define RS 80   // smem row stride in bytes (64B payload + pad)
#define ASZ (128 * RS)          // one A buffer (10240 B)

// ---------------- scratch ----------------
__device__ __nv_bfloat16 g_ahi[256 * 32768];
__device__ __nv_bfloat16 g_alo[256 * 32768];
__device__ __nv_bfloat16 g_bhi[256 * 16384];
__device__ __nv_bfloat16 g_blo[256 * 16384];
__device__ __nv_bfloat16 g_whi[16 * 256 * 512];
__device__ __nv_bfloat16 g_wlo[16 * 256 * 512];
__device__ float g_part[2 * 256 * 8192];   // split-K partials (16MB)
__device__ int   g_cnt[256];               // last-CTA counters (zero-init)

// ---------------- helpers ----------------
__device__ __forceinline__ void ldsm_x4(uint32_t* r, uint32_t addr) {
    asm volatile("ldmatrix.sync.aligned.m8n8.x4.shared.b16 {%0,%1,%2,%3}, [%4];"
        : "=r"(r[0]), "=r"(r[1]), "=r"(r[2]), "=r"(r[3]) : "r"(addr));
}

__device__ __forceinline__ void mma_bf16(float* c, const uint32_t* a, const uint32_t* b) {
    asm volatile(
        "mma.sync.aligned.m16n8k16.row.col.f32.bf16.bf16.f32 "
        "{%0,%1,%2,%3}, {%4,%5,%6,%7}, {%8,%9}, {%0,%1,%2,%3};"
        : "+f"(c[0]), "+f"(c[1]), "+f"(c[2]), "+f"(c[3])
        : "r"(a[0]), "r"(a[1]), "r"(a[2]), "r"(a[3]), "r"(b[0]), "r"(b[1]));
}

__device__ __forceinline__ void split2(float x, float y, uint32_t& h, uint32_t& l) {
    __nv_bfloat16 hx = __float2bfloat16(x);
    __nv_bfloat16 hy = __float2bfloat16(y);
    __nv_bfloat162 hp; hp.x = hx; hp.y = hy;
    __nv_bfloat162 lp;
    lp.x = __float2bfloat16(x - __bfloat162float(hx));
    lp.y = __float2bfloat16(y - __bfloat162float(hy));
    h = *reinterpret_cast<uint32_t*>(&hp);
    l = *reinterpret_cast<uint32_t*>(&lp);
}

// ---------------- weight hi/lo split ----------------
__global__ void prep_w(const float* __restrict__ W,
                       __nv_bfloat16* __restrict__ hi,
                       __nv_bfloat16* __restrict__ lo, int n) {
    int i = blockIdx.x * blockDim.x + threadIdx.x;
    if (i < n) {
        float v = W[i];
        __nv_bfloat16 h = __float2bfloat16(v);
        hi[i] = h;
        lo[i] = __float2bfloat16(v - __bfloat162float(h));
    }
}

// ---------------- per-layer GEMM kernel ----------------
// CTA: 256 threads = 8 warps; tile 128 x NT, BK=32.
// NT=128: 2(M) x 4(N) warp grid (per-warp 64x32) — proven mapping.
// NT=64 : 4(M) x 2(N) warp grid (per-warp 32x32) — lower A duplication.
// Split-K: blockIdx.z = split, cs chunks each; last CTA per (x,y) tile
// reduces partials + bias + tanh + hi/lo split.
template<int NT>
__global__ __launch_bounds__(256) void layer_hmma(
    const void* __restrict__ in_hi,
    const __nv_bfloat16* __restrict__ in_lo,
    const __nv_bfloat16* __restrict__ Whi,   // 256 x 512
    const __nv_bfloat16* __restrict__ Wlo,
    const float* __restrict__ bias,
    __nv_bfloat16* __restrict__ out_hi,
    __nv_bfloat16* __restrict__ out_lo,
    float* __restrict__ out_f,
    float* __restrict__ gpart,               // non-null -> split mode
    int* __restrict__ cnt,
    int Nin, int Nout, int fp32_in, int cs)
{
    constexpr int WM   = (NT == 128) ? 2 : 4;   // warps along M
    constexpr int MR   = 128 / WM;              // rows per warp (64 / 32)
    constexpr int MT   = MR / 16;               // m16 tiles per warp (4 / 2)
    constexpr int SEGT = NT / 8;
    constexpr int BSZ  = NT * RS;

    extern __shared__ __align__(16) char smem[];
    const uint32_t su = (uint32_t)__cvta_generic_to_shared(smem);
    const uint32_t uAH = su;
    const uint32_t uAL = su + 2 * ASZ;
    const uint32_t uBH = su + 4 * ASZ;
    const uint32_t uBL = su + 4 * ASZ + 2 * BSZ;

    const int tid  = threadIdx.x;
    const int lane = tid & 31;
    const int wid  = tid >> 5;
    const int wm   = (NT == 128) ? (wid & 1) : (wid >> 1);
    const int wn   = (NT == 128) ? (wid >> 1) : (wid & 1);
    const int m0   = blockIdx.y * 128;
    const int j0   = blockIdx.x * NT;
    const int kb   = blockIdx.z * cs;
    const int ke   = kb + cs;

    float acc[MT][4][4];
    #pragma unroll
    for (int a = 0; a < MT; a++)
        #pragma unroll
        for (int b = 0; b < 4; b++)
            #pragma unroll
            for (int c = 0; c < 4; c++) acc[a][b][c] = 0.f;

    const int a_row = lane & 15;
    const int a_cb  = lane >> 4;
    const int b_row = (lane & 7) + ((lane >> 4) << 3);
    const int b_cb  = (lane >> 3) & 1;

    const int l_arow = tid >> 1, l_ahalf = tid & 1;
    const int l_c = tid & 15, l_seg = tid >> 4;

    uint4 pAh0, pAh1, pAl0, pAl1;
    uint32_t pBh[SEGT / 2], pBl[SEGT / 2];

    auto load_g = [&](int chunk) {
        const int k0 = chunk * 32;
        {
            size_t gofs = (size_t)(m0 + l_arow) * 512 + k0 + l_ahalf * 16;
            const uint4* ph = reinterpret_cast<const uint4*>(Whi + gofs);
            const uint4* pl = reinterpret_cast<const uint4*>(Wlo + gofs);
            pAh0 = ph[0]; pAh1 = ph[1];
            pAl0 = pl[0]; pAl1 = pl[1];
        }
        {
            const int ch = (k0 >> 1) + l_c;
            const int t  = 2 * j0 + l_seg * SEGT;
            if (fp32_in) {
                const float* p = reinterpret_cast<const float*>(in_hi) + (size_t)ch * Nin + t;
                if (t + SEGT - 1 < Nin) {
                    #pragma unroll
                    for (int q = 0; q < SEGT / 4; q++) {
                        float4 f = reinterpret_cast<const float4*>(p)[q];
                        split2(f.x, f.y, pBh[2 * q],     pBl[2 * q]);
                        split2(f.z, f.w, pBh[2 * q + 1], pBl[2 * q + 1]);
                    }
                } else {
                    #pragma unroll
                    for (int q = 0; q < SEGT / 2; q++) {
                        float f0 = (t + 2 * q     < Nin) ? p[2 * q]     : 0.f;
                        float f1 = (t + 2 * q + 1 < Nin) ? p[2 * q + 1] : 0.f;
                        split2(f0, f1, pBh[q], pBl[q]);
                    }
                }
            } else {
                const __nv_bfloat16* ph = reinterpret_cast<const __nv_bfloat16*>(in_hi) + (size_t)ch * Nin + t;
                const __nv_bfloat16* pl = in_lo + (size_t)ch * Nin + t;
                if (t + SEGT - 1 < Nin) {
                    #pragma unroll
                    for (int q = 0; q < SEGT / 8; q++) {
                        uint4 uh = reinterpret_cast<const uint4*>(ph)[q];
                        uint4 ul = reinterpret_cast<const uint4*>(pl)[q];
                        pBh[4 * q + 0] = uh.x; pBh[4 * q + 1] = uh.y;
                        pBh[4 * q + 2] = uh.z; pBh[4 * q + 3] = uh.w;
                        pBl[4 * q + 0] = ul.x; pBl[4 * q + 1] = ul.y;
                        pBl[4 * q + 2] = ul.z; pBl[4 * q + 3] = ul.w;
                    }
                } else {
                    #pragma unroll
                    for (int q = 0; q < SEGT / 2; q++) {
                        __nv_bfloat162 hp, lp;
                        hp.x = (t + 2 * q     < Nin) ? ph[2 * q]     : __nv_bfloat16(0.f);
                        hp.y = (t + 2 * q + 1 < Nin) ? ph[2 * q + 1] : __nv_bfloat16(0.f);
                        lp.x = (t + 2 * q     < Nin) ? pl[2 * q]     : __nv_bfloat16(0.f);
                        lp.y = (t + 2 * q + 1 < Nin) ? pl[2 * q + 1] : __nv_bfloat16(0.f);
                        pBh[q] = *reinterpret_cast<uint32_t*>(&hp);
                        pBl[q] = *reinterpret_cast<uint32_t*>(&lp);
                    }
                }
            }
        }
    };

    auto store_smem = [&](int buf) {
        char* base = smem;
        char* dh = base + buf * ASZ + l_arow * RS + l_ahalf * 32;
        char* dl = base + 2 * ASZ + buf * ASZ + l_arow * RS + l_ahalf * 32;
        reinterpret_cast<uint4*>(dh)[0] = pAh0;
        reinterpret_cast<uint4*>(dh)[1] = pAh1;
        reinterpret_cast<uint4*>(dl)[0] = pAl0;
        reinterpret_cast<uint4*>(dl)[1] = pAl1;
        char* dbh = base + 4 * ASZ + buf * BSZ + (l_seg * (SEGT / 2)) * RS + 4 * l_c;
        char* dbl = base + 4 * ASZ + 2 * BSZ + buf * BSZ + (l_seg * (SEGT / 2)) * RS + 4 * l_c;
        #pragma unroll
        for (int q = 0; q < SEGT / 2; q++) {
            *reinterpret_cast<uint32_t*>(dbh + q * RS) = pBh[q];
            *reinterpret_cast<uint32_t*>(dbl + q * RS) = pBl[q];
        }
    };

    load_g(kb);
    store_smem(0);
    if (kb + 1 < ke) load_g(kb + 1);
    __syncthreads();

    for (int chunk = kb; chunk < ke; chunk++) {
        const int buf = (chunk - kb) & 1;
        const uint32_t aH = uAH + buf * ASZ;
        const uint32_t aL = uAL + buf * ASZ;
        const uint32_t bH = uBH + buf * BSZ;
        const uint32_t bL = uBL + buf * BSZ;

        #pragma unroll
        for (int ks = 0; ks < 2; ks++) {
            uint32_t ah[MT][4], al[MT][4], bh[4][2], bl[4][2];
            #pragma unroll
            for (int mt = 0; mt < MT; mt++) {
                uint32_t ofs = (uint32_t)((wm * MR + mt * 16 + a_row) * RS + ks * 32 + a_cb * 16);
                ldsm_x4(ah[mt], aH + ofs);
            }
            #pragma unroll
            for (int half = 0; half < 2; half++) {
                uint32_t ofs = (uint32_t)((wn * 32 + half * 16 + b_row) * RS + ks * 32 + b_cb * 16);
                uint32_t r[4];
                ldsm_x4(r, bH + ofs);
                bh[half * 2][0] = r[0]; bh[half * 2][1] = r[1];
                bh[half * 2 + 1][0] = r[2]; bh[half * 2 + 1][1] = r[3];
                ldsm_x4(r, bL + ofs);
                bl[half * 2][0] = r[0]; bl[half * 2][1] = r[1];
                bl[half * 2 + 1][0] = r[2]; bl[half * 2 + 1][1] = r[3];
            }
            #pragma unroll
            for (int mt = 0; mt < MT; mt++) {
                uint32_t ofs = (uint32_t)((wm * MR + mt * 16 + a_row) * RS + ks * 32 + a_cb * 16);
                ldsm_x4(al[mt], aL + ofs);
            }
            #pragma unroll
            for (int mt = 0; mt < MT; mt++)
                #pragma unroll
                for (int nt = 0; nt < 4; nt++) {
                    mma_bf16(acc[mt][nt], ah[mt], bh[nt]);
                    mma_bf16(acc[mt][nt], ah[mt], bl[nt]);
                }
            #pragma unroll
            for (int mt = 0; mt < MT; mt++)
                #pragma unroll
                for (int nt = 0; nt < 4; nt++)
                    mma_bf16(acc[mt][nt], al[mt], bh[nt]);
        }

        if (chunk + 1 < ke) {
            store_smem((chunk + 1 - kb) & 1);
            if (chunk + 2 < ke) load_g(chunk + 2);
        }
        __syncthreads();
    }

    const int g = lane >> 2, tig = lane & 3;

    if (gpart) {
        // ---- split mode: store fp32 partials ----
        float* gp = gpart + (size_t)blockIdx.z * 256 * Nout;
        #pragma unroll
        for (int mt = 0; mt < MT; mt++) {
            const int mA = m0 + wm * MR + mt * 16 + g;
            const int mB = mA + 8;
            #pragma unroll
            for (int nt = 0; nt < 4; nt++) {
                const int col = j0 + wn * 32 + nt * 8 + 2 * tig;
                if (col < Nout) {
                    gp[(size_t)mA * Nout + col] = acc[mt][nt][0];
                    gp[(size_t)mB * Nout + col] = acc[mt][nt][2];
                    if (col + 1 < Nout) {
                        gp[(size_t)mA * Nout + col + 1] = acc[mt][nt][1];
                        gp[(size_t)mB * Nout + col + 1] = acc[mt][nt][3];
                    }
                }
            }
        }
        // ---- last-CTA-done reduction ----
        __threadfence();
        __shared__ int s_last;
        const int tileid = blockIdx.y * gridDim.x + blockIdx.x;
        if (tid == 0)
            s_last = (atomicAdd(&cnt[tileid], 1) == (int)gridDim.z - 1);
        __syncthreads();
        if (!s_last) return;
        if (tid == 0) cnt[tileid] = 0;   // reset for graph replay / next layer

        const int S = gridDim.z;
        const int stride = 256 * Nout;
        if (out_f) {                     // final layer, Nout == 1
            for (int r = tid; r < 128; r += 256) {
                int mrow = m0 + r;
                float s = bias[mrow];
                for (int q = 0; q < S; q++) s += gpart[q * stride + mrow];
                out_f[mrow] = tanhf(s);
            }
            return;
        }
        for (int idx = tid; idx < 128 * (NT / 2); idx += 256) {
            int r  = idx / (NT / 2);
            int jp = idx % (NT / 2);
            int mrow = m0 + r;
            int col  = j0 + 2 * jp;
            if (col + 1 < Nout || (col < Nout && Nout >= 2)) {
                if (col + 1 <= Nout - 1) {
                    float s0 = bias[mrow], s1 = s0;
                    const float* p = gpart + (size_t)mrow * Nout + col;
                    for (int q = 0; q < S; q++) {
                        s0 += p[q * stride];
                        s1 += p[q * stride + 1];
                    }
                    uint32_t h, l;
                    split2(tanhf(s0), tanhf(s1), h, l);
                    *reinterpret_cast<uint32_t*>(out_hi + (size_t)mrow * Nout + col) = h;
                    *reinterpret_cast<uint32_t*>(out_lo + (size_t)mrow * Nout + col) = l;
                }
            }
        }
        return;
    }

    // ---- unsplit epilogue ----
    #pragma unroll
    for (int mt = 0; mt < MT; mt++) {
        const int mA = m0 + wm * MR + mt * 16 + g;
        const int mB = mA + 8;
        const float bA = bias[mA], bB = bias[mB];
        #pragma unroll
        for (int nt = 0; nt < 4; nt++) {
            const int col = j0 + wn * 32 + nt * 8 + 2 * tig;
            float v0 = tanhf(acc[mt][nt][0] + bA);
            float v1 = tanhf(acc[mt][nt][1] + bA);
            float v2 = tanhf(acc[mt][nt][2] + bB);
            float v3 = tanhf(acc[mt][nt][3] + bB);
            if (out_f) {
                if (col == 0) { out_f[mA] = v0; out_f[mB] = v2; }
            } else if (col < Nout) {
                uint32_t h, l;
                split2(v0, v1, h, l);
                *reinterpret_cast<uint32_t*>(out_hi + (size_t)mA * Nout + col) = h;
                *reinterpret_cast<uint32_t*>(out_lo + (size_t)mA * Nout + col) = l;
                split2(v2, v3, h, l);
                *reinterpret_cast<uint32_t*>(out_hi + (size_t)mB * Nout + col) = h;
                *reinterpret_cast<uint32_t*>(out_lo + (size_t)mB * Nout + col) = l;
            }
        }
    }
}

// ---------------- host ----------------
extern "C" void kernel_launch(void* const* d_in, const int* in_sizes, int n_in,
                              void* d_out, int out_size)
{
    const float* x = (const float*)d_in[0];
    const float* W = (const float*)d_in[1];
    const float* b = (const float*)d_in[2];

    __nv_bfloat16 *ahi, *alo, *bhi, *blo, *whi, *wlo;
    float* gpart; int* cnt;
    cudaGetSymbolAddress((void**)&ahi, g_ahi);
    cudaGetSymbolAddress((void**)&alo, g_alo);
    cudaGetSymbolAddress((void**)&bhi, g_bhi);
    cudaGetSymbolAddress((void**)&blo, g_blo);
    cudaGetSymbolAddress((void**)&whi, g_whi);
    cudaGetSymbolAddress((void**)&wlo, g_wlo);
    cudaGetSymbolAddress((void**)&gpart, g_part);
    cudaGetSymbolAddress((void**)&cnt, g_cnt);

    const int smem128 = 4 * ASZ + 4 * 128 * RS;   // 81920
    const int smem64  = 4 * ASZ + 4 * 64 * RS;    // 61440
    cudaFuncSetAttribute(layer_hmma<128>, cudaFuncAttributeMaxDynamicSharedMemorySize, smem128);
    cudaFuncSetAttribute(layer_hmma<64>,  cudaFuncAttributeMaxDynamicSharedMemorySize, smem64);

    const int nW = 16 * 256 * 512;
    prep_w<<<(nW + 255) / 256, 256>>>(W, whi, wlo, nW);

    int Nin = 65536;
    const void* cur_hi = (const void*)x;
    const __nv_bfloat16* cur_lo = nullptr;
    int fp32_in = 1;

    for (int i = 0; i < 16; i++) {
        int Nout = Nin >> 1;
        __nv_bfloat16* ohi = (i & 1) ? bhi : ahi;
        __nv_bfloat16* olo = (i & 1) ? blo : alo;
        float* of = (i == 15) ? (float*)d_out : nullptr;

        if (Nout >= 16384) {
            // layers 0-1: NT128 unsplit
            dim3 grid(Nout / 128, 2);
            layer_hmma<128><<<grid, 256, smem128>>>(cur_hi, cur_lo,
                whi + (size_t)i * 256 * 512, wlo + (size_t)i * 256 * 512,
                b + i * 256, ohi, olo, of, nullptr, cnt, Nin, Nout, fp32_in, 16);
        } else if (Nout >= 8192) {
            // layer 2: NT128, S=2 split
            dim3 grid(Nout / 128, 2, 2);
            layer_hmma<128><<<grid, 256, smem128>>>(cur_hi, cur_lo,
                whi + (size_t)i * 256 * 512, wlo + (size_t)i * 256 * 512,
                b + i * 256, ohi, olo, of, gpart, cnt, Nin, Nout, fp32_in, 8);
        } else {
            int gx = (Nout + 63) / 64;
            int base = gx * 2;
            int S = (base >= 256) ? 1 : ((256 / base >= 4) ? 4 : 2);
            if (S == 1) {
                dim3 grid(gx, 2);
                layer_hmma<64><<<grid, 256, smem64>>>(cur_hi, cur_lo,
                    whi + (size_t)i * 256 * 512, wlo + (size_t)i * 256 * 512,
                    b + i * 256, ohi, olo, of, nullptr, cnt, Nin, Nout, fp32_in, 16);
            } else {
                dim3 grid(gx, 2, S);
                layer_hmma<64><<<grid, 256, smem64>>>(cur_hi, cur_lo,
                    whi + (size_t)i * 256 * 512, wlo + (size_t)i * 256 * 512,
                    b + i * 256, ohi, olo, of, gpart, cnt, Nin, Nout, fp32_in, 16 / S);
            }
        }
        cur_hi = (const void*)ohi;
        cur_lo = olo;
        fp32_in = 0;
        Nin = Nout;
    }
}

// round 15
// speedup vs baseline: 1.4451x; 1.4451x over previous
#include <cuda_runtime.h>
#include <cuda_bf16.h>
#include <cstdint>
#include <math.h>

// ============================================================
// bf16-split GEMM per layer via mma.sync (HMMA).
//   layer i: out[c,j] = tanh( sum_k W[c,k]*B[k,j] + bias[c] )
//   B[k][j] = in[k>>1][2j + (k&1)]   (compacted dilated conv)
//   fp32 ~= bf16 hi+lo:  A*B ~= Ah*Bh + Ah*Bl + Al*Bh
// R15: exact R13 revert (best: 416us) + ONE change:
//   adaptive split-K depth S in {1,2,4,8,16}, chosen so the
//   layer fills ~256 CTAs (one wave at 2 CTA/SM). Separate
//   reduce kernel retained (R14's fused reduce regressed).
// ============================================================

#define RS 80   // smem row stride in bytes (64B payload + pad)
#define ASZ (128 * RS)          // one A buffer (10240 B)

// ---------------- scratch ----------------
__device__ __nv_bfloat16 g_ahi[256 * 32768];
__device__ __nv_bfloat16 g_alo[256 * 32768];
__device__ __nv_bfloat16 g_bhi[256 * 16384];
__device__ __nv_bfloat16 g_blo[256 * 16384];
__device__ __nv_bfloat16 g_whi[16 * 256 * 512];
__device__ __nv_bfloat16 g_wlo[16 * 256 * 512];
__device__ float g_part[16 * 256 * 4096];   // split-K partials (64MB)

// ---------------- helpers ----------------
__device__ __forceinline__ void ldsm_x4(uint32_t* r, uint32_t addr) {
    asm volatile("ldmatrix.sync.aligned.m8n8.x4.shared.b16 {%0,%1,%2,%3}, [%4];"
        : "=r"(r[0]), "=r"(r[1]), "=r"(r[2]), "=r"(r[3]) : "r"(addr));
}

__device__ __forceinline__ void mma_bf16(float* c, const uint32_t* a, const uint32_t* b) {
    asm volatile(
        "mma.sync.aligned.m16n8k16.row.col.f32.bf16.bf16.f32 "
        "{%0,%1,%2,%3}, {%4,%5,%6,%7}, {%8,%9}, {%0,%1,%2,%3};"
        : "+f"(c[0]), "+f"(c[1]), "+f"(c[2]), "+f"(c[3])
        : "r"(a[0]), "r"(a[1]), "r"(a[2]), "r"(a[3]), "r"(b[0]), "r"(b[1]));
}

__device__ __forceinline__ void split2(float x, float y, uint32_t& h, uint32_t& l) {
    __nv_bfloat16 hx = __float2bfloat16(x);
    __nv_bfloat16 hy = __float2bfloat16(y);
    __nv_bfloat162 hp; hp.x = hx; hp.y = hy;
    __nv_bfloat162 lp;
    lp.x = __float2bfloat16(x - __bfloat162float(hx));
    lp.y = __float2bfloat16(y - __bfloat162float(hy));
    h = *reinterpret_cast<uint32_t*>(&hp);
    l = *reinterpret_cast<uint32_t*>(&lp);
}

// ---------------- weight hi/lo split ----------------
__global__ void prep_w(const float* __restrict__ W,
                       __nv_bfloat16* __restrict__ hi,
                       __nv_bfloat16* __restrict__ lo, int n) {
    int i = blockIdx.x * blockDim.x + threadIdx.x;
    if (i < n) {
        float v = W[i];
        __nv_bfloat16 h = __float2bfloat16(v);
        hi[i] = h;
        lo[i] = __float2bfloat16(v - __bfloat162float(h));
    }
}

// ---------------- split-K reduce: sum + bias + tanh + split ----------------
__global__ void reduce_k(const float* __restrict__ gpart, int S,
                         const float* __restrict__ bias, int Nout,
                         __nv_bfloat16* __restrict__ out_hi,
                         __nv_bfloat16* __restrict__ out_lo,
                         float* __restrict__ out_f) {
    const int stride = 256 * Nout;
    if (out_f) {                               // final layer: Nout == 1
        int c = blockIdx.x * blockDim.x + threadIdx.x;
        if (c < 256) {
            float s = bias[c];
            for (int q = 0; q < S; q++) s += gpart[q * stride + c];
            out_f[c] = tanhf(s);
        }
        return;
    }
    const int np = Nout >> 1;                  // pairs per channel
    int idx = blockIdx.x * blockDim.x + threadIdx.x;
    if (idx < 256 * np) {
        int c = idx / np, jp = idx % np, j = 2 * jp;
        float s0 = bias[c], s1 = s0;
        const float* p = gpart + c * Nout + j;
        for (int q = 0; q < S; q++) {
            s0 += p[q * stride];
            s1 += p[q * stride + 1];
        }
        float v0 = tanhf(s0), v1 = tanhf(s1);
        uint32_t h, l;
        split2(v0, v1, h, l);
        *reinterpret_cast<uint32_t*>(out_hi + (size_t)c * Nout + j) = h;
        *reinterpret_cast<uint32_t*>(out_lo + (size_t)c * Nout + j) = l;
    }
}

// ---------------- per-layer GEMM kernel ----------------
// CTA: 256 threads = 8 warps in 2(M) x 4(N); tile 128 x NT, BK=32.
// Chunks [kb, ke). gpart != null -> fp32 partial store (split blockIdx.z).
template<int NT>
__global__ __launch_bounds__(256) void layer_hmma(
    const void* __restrict__ in_hi,
    const __nv_bfloat16* __restrict__ in_lo,
    const __nv_bfloat16* __restrict__ Whi,   // 256 x 512
    const __nv_bfloat16* __restrict__ Wlo,
    const float* __restrict__ bias,
    __nv_bfloat16* __restrict__ out_hi,
    __nv_bfloat16* __restrict__ out_lo,
    float* __restrict__ out_f,
    float* __restrict__ gpart,
    int Nin, int Nout, int fp32_in, int cs)   // cs = chunks per split
{
    constexpr int NTT   = NT / 32;
    constexpr int NHALF = NT / 64;
    constexpr int SEGT  = NT / 8;
    constexpr int BSZ   = NT * RS;

    extern __shared__ __align__(16) char smem[];
    const uint32_t su = (uint32_t)__cvta_generic_to_shared(smem);
    const uint32_t uAH = su;
    const uint32_t uAL = su + 2 * ASZ;
    const uint32_t uBH = su + 4 * ASZ;
    const uint32_t uBL = su + 4 * ASZ + 2 * BSZ;

    const int tid  = threadIdx.x;
    const int lane = tid & 31;
    const int wid  = tid >> 5;
    const int wm   = wid & 1;
    const int wn   = wid >> 1;
    const int m0   = blockIdx.y * 128;
    const int j0   = blockIdx.x * NT;
    const int kb   = blockIdx.z * cs;
    const int ke   = kb + cs;

    float acc[4][NTT][4];
    #pragma unroll
    for (int a = 0; a < 4; a++)
        #pragma unroll
        for (int b = 0; b < NTT; b++)
            #pragma unroll
            for (int c = 0; c < 4; c++) acc[a][b][c] = 0.f;

    const int a_row = lane & 15;
    const int a_cb  = lane >> 4;
    const int b_row = (lane & 7) + ((lane >> 4) << 3);
    const int b_cb  = (lane >> 3) & 1;

    const int l_arow = tid >> 1, l_ahalf = tid & 1;
    const int l_c = tid & 15, l_seg = tid >> 4;

    uint4 pAh0, pAh1, pAl0, pAl1;
    uint32_t pBh[SEGT / 2], pBl[SEGT / 2];

    auto load_g = [&](int chunk) {
        const int k0 = chunk * 32;
        {
            size_t gofs = (size_t)(m0 + l_arow) * 512 + k0 + l_ahalf * 16;
            const uint4* ph = reinterpret_cast<const uint4*>(Whi + gofs);
            const uint4* pl = reinterpret_cast<const uint4*>(Wlo + gofs);
            pAh0 = ph[0]; pAh1 = ph[1];
            pAl0 = pl[0]; pAl1 = pl[1];
        }
        {
            const int ch = (k0 >> 1) + l_c;
            const int t  = 2 * j0 + l_seg * SEGT;
            if (fp32_in) {
                const float* p = reinterpret_cast<const float*>(in_hi) + (size_t)ch * Nin + t;
                if (t + SEGT - 1 < Nin) {
                    #pragma unroll
                    for (int q = 0; q < SEGT / 4; q++) {
                        float4 f = reinterpret_cast<const float4*>(p)[q];
                        split2(f.x, f.y, pBh[2 * q],     pBl[2 * q]);
                        split2(f.z, f.w, pBh[2 * q + 1], pBl[2 * q + 1]);
                    }
                } else {
                    #pragma unroll
                    for (int q = 0; q < SEGT / 2; q++) {
                        float f0 = (t + 2 * q     < Nin) ? p[2 * q]     : 0.f;
                        float f1 = (t + 2 * q + 1 < Nin) ? p[2 * q + 1] : 0.f;
                        split2(f0, f1, pBh[q], pBl[q]);
                    }
                }
            } else {
                const __nv_bfloat16* ph = reinterpret_cast<const __nv_bfloat16*>(in_hi) + (size_t)ch * Nin + t;
                const __nv_bfloat16* pl = in_lo + (size_t)ch * Nin + t;
                if (t + SEGT - 1 < Nin) {
                    #pragma unroll
                    for (int q = 0; q < SEGT / 8; q++) {
                        uint4 uh = reinterpret_cast<const uint4*>(ph)[q];
                        uint4 ul = reinterpret_cast<const uint4*>(pl)[q];
                        pBh[4 * q + 0] = uh.x; pBh[4 * q + 1] = uh.y;
                        pBh[4 * q + 2] = uh.z; pBh[4 * q + 3] = uh.w;
                        pBl[4 * q + 0] = ul.x; pBl[4 * q + 1] = ul.y;
                        pBl[4 * q + 2] = ul.z; pBl[4 * q + 3] = ul.w;
                    }
                } else {
                    #pragma unroll
                    for (int q = 0; q < SEGT / 2; q++) {
                        __nv_bfloat162 hp, lp;
                        hp.x = (t + 2 * q     < Nin) ? ph[2 * q]     : __nv_bfloat16(0.f);
                        hp.y = (t + 2 * q + 1 < Nin) ? ph[2 * q + 1] : __nv_bfloat16(0.f);
                        lp.x = (t + 2 * q     < Nin) ? pl[2 * q]     : __nv_bfloat16(0.f);
                        lp.y = (t + 2 * q + 1 < Nin) ? pl[2 * q + 1] : __nv_bfloat16(0.f);
                        pBh[q] = *reinterpret_cast<uint32_t*>(&hp);
                        pBl[q] = *reinterpret_cast<uint32_t*>(&lp);
                    }
                }
            }
        }
    };

    auto store_smem = [&](int buf) {
        char* base = smem;
        char* dh = base + buf * ASZ + l_arow * RS + l_ahalf * 32;
        char* dl = base + 2 * ASZ + buf * ASZ + l_arow * RS + l_ahalf * 32;
        reinterpret_cast<uint4*>(dh)[0] = pAh0;
        reinterpret_cast<uint4*>(dh)[1] = pAh1;
        reinterpret_cast<uint4*>(dl)[0] = pAl0;
        reinterpret_cast<uint4*>(dl)[1] = pAl1;
        char* dbh = base + 4 * ASZ + buf * BSZ + (l_seg * (SEGT / 2)) * RS + 4 * l_c;
        char* dbl = base + 4 * ASZ + 2 * BSZ + buf * BSZ + (l_seg * (SEGT / 2)) * RS + 4 * l_c;
        #pragma unroll
        for (int q = 0; q < SEGT / 2; q++) {
            *reinterpret_cast<uint32_t*>(dbh + q * RS) = pBh[q];
            *reinterpret_cast<uint32_t*>(dbl + q * RS) = pBl[q];
        }
    };

    load_g(kb);
    store_smem(0);
    if (kb + 1 < ke) load_g(kb + 1);
    __syncthreads();

    for (int chunk = kb; chunk < ke; chunk++) {
        const int buf = (chunk - kb) & 1;
        const uint32_t aH = uAH + buf * ASZ;
        const uint32_t aL = uAL + buf * ASZ;
        const uint32_t bH = uBH + buf * BSZ;
        const uint32_t bL = uBL + buf * BSZ;

        #pragma unroll
        for (int ks = 0; ks < 2; ks++) {
            uint32_t ah[4][4], al[4][4], bh[NTT][2], bl[NTT][2];
            #pragma unroll
            for (int mt = 0; mt < 4; mt++) {
                uint32_t ofs = (uint32_t)((wm * 64 + mt * 16 + a_row) * RS + ks * 32 + a_cb * 16);
                ldsm_x4(ah[mt], aH + ofs);
            }
            #pragma unroll
            for (int half = 0; half < NHALF; half++) {
                uint32_t ofs = (uint32_t)((wn * (NT / 4) + half * 16 + b_row) * RS + ks * 32 + b_cb * 16);
                uint32_t r[4];
                ldsm_x4(r, bH + ofs);
                bh[half * 2][0] = r[0]; bh[half * 2][1] = r[1];
                bh[half * 2 + 1][0] = r[2]; bh[half * 2 + 1][1] = r[3];
                ldsm_x4(r, bL + ofs);
                bl[half * 2][0] = r[0]; bl[half * 2][1] = r[1];
                bl[half * 2 + 1][0] = r[2]; bl[half * 2 + 1][1] = r[3];
            }
            #pragma unroll
            for (int mt = 0; mt < 4; mt++) {
                uint32_t ofs = (uint32_t)((wm * 64 + mt * 16 + a_row) * RS + ks * 32 + a_cb * 16);
                ldsm_x4(al[mt], aL + ofs);
            }
            #pragma unroll
            for (int mt = 0; mt < 4; mt++)
                #pragma unroll
                for (int nt = 0; nt < NTT; nt++) {
                    mma_bf16(acc[mt][nt], ah[mt], bh[nt]);
                    mma_bf16(acc[mt][nt], ah[mt], bl[nt]);
                }
            #pragma unroll
            for (int mt = 0; mt < 4; mt++)
                #pragma unroll
                for (int nt = 0; nt < NTT; nt++)
                    mma_bf16(acc[mt][nt], al[mt], bh[nt]);
        }

        if (chunk + 1 < ke) {
            store_smem((chunk + 1 - kb) & 1);
            if (chunk + 2 < ke) load_g(chunk + 2);
        }
        __syncthreads();
    }

    // ---- epilogue ----
    const int g = lane >> 2, tig = lane & 3;
    if (gpart) {
        // raw fp32 partial store (no bias/tanh)
        float* gp = gpart + (size_t)blockIdx.z * 256 * Nout;
        #pragma unroll
        for (int mt = 0; mt < 4; mt++) {
            const int mA = m0 + wm * 64 + mt * 16 + g;
            const int mB = mA + 8;
            #pragma unroll
            for (int nt = 0; nt < NTT; nt++) {
                const int col = j0 + wn * (NT / 4) + nt * 8 + 2 * tig;
                if (col < Nout) {
                    gp[(size_t)mA * Nout + col] = acc[mt][nt][0];
                    gp[(size_t)mB * Nout + col] = acc[mt][nt][2];
                    if (col + 1 < Nout) {
                        gp[(size_t)mA * Nout + col + 1] = acc[mt][nt][1];
                        gp[(size_t)mB * Nout + col + 1] = acc[mt][nt][3];
                    }
                }
            }
        }
        return;
    }
    #pragma unroll
    for (int mt = 0; mt < 4; mt++) {
        const int mA = m0 + wm * 64 + mt * 16 + g;
        const int mB = mA + 8;
        const float bA = bias[mA], bB = bias[mB];
        #pragma unroll
        for (int nt = 0; nt < NTT; nt++) {
            const int col = j0 + wn * (NT / 4) + nt * 8 + 2 * tig;
            float v0 = tanhf(acc[mt][nt][0] + bA);
            float v1 = tanhf(acc[mt][nt][1] + bA);
            float v2 = tanhf(acc[mt][nt][2] + bB);
            float v3 = tanhf(acc[mt][nt][3] + bB);
            if (out_f) {
                if (col == 0) { out_f[mA] = v0; out_f[mB] = v2; }
            } else if (col < Nout) {
                uint32_t h, l;
                split2(v0, v1, h, l);
                *reinterpret_cast<uint32_t*>(out_hi + (size_t)mA * Nout + col) = h;
                *reinterpret_cast<uint32_t*>(out_lo + (size_t)mA * Nout + col) = l;
                split2(v2, v3, h, l);
                *reinterpret_cast<uint32_t*>(out_hi + (size_t)mB * Nout + col) = h;
                *reinterpret_cast<uint32_t*>(out_lo + (size_t)mB * Nout + col) = l;
            }
        }
    }
}

// ---------------- host ----------------
extern "C" void kernel_launch(void* const* d_in, const int* in_sizes, int n_in,
                              void* d_out, int out_size)
{
    const float* x = (const float*)d_in[0];
    const float* W = (const float*)d_in[1];
    const float* b = (const float*)d_in[2];

    __nv_bfloat16 *ahi, *alo, *bhi, *blo, *whi, *wlo;
    float* gpart;
    cudaGetSymbolAddress((void**)&ahi, g_ahi);
    cudaGetSymbolAddress((void**)&alo, g_alo);
    cudaGetSymbolAddress((void**)&bhi, g_bhi);
    cudaGetSymbolAddress((void**)&blo, g_blo);
    cudaGetSymbolAddress((void**)&whi, g_whi);
    cudaGetSymbolAddress((void**)&wlo, g_wlo);
    cudaGetSymbolAddress((void**)&gpart, g_part);

    const int smem128 = 4 * ASZ + 4 * 128 * RS;   // 81920
    const int smem64  = 4 * ASZ + 4 * 64 * RS;    // 61440
    cudaFuncSetAttribute(layer_hmma<128>, cudaFuncAttributeMaxDynamicSharedMemorySize, smem128);
    cudaFuncSetAttribute(layer_hmma<64>,  cudaFuncAttributeMaxDynamicSharedMemorySize, smem64);

    const int nW = 16 * 256 * 512;
    prep_w<<<(nW + 255) / 256, 256>>>(W, whi, wlo, nW);

    int Nin = 65536;
    const void* cur_hi = (const void*)x;
    const __nv_bfloat16* cur_lo = nullptr;
    int fp32_in = 1;

    for (int i = 0; i < 16; i++) {
        int Nout = Nin >> 1;
        __nv_bfloat16* ohi = (i & 1) ? bhi : ahi;
        __nv_bfloat16* olo = (i & 1) ? blo : alo;
        float* of = (i == 15) ? (float*)d_out : nullptr;

        if (Nout >= 16384) {
            dim3 grid((Nout + 127) / 128, 2);
            layer_hmma<128><<<grid, 256, smem128>>>(cur_hi, cur_lo,
                whi + (size_t)i * 256 * 512, wlo + (size_t)i * 256 * 512,
                b + i * 256, ohi, olo, of, nullptr, Nin, Nout, fp32_in, 16);
        } else {
            int gx = (Nout + 63) / 64;
            int base = gx * 2;
            // adaptive split depth: fill ~256 CTAs, S in {1,2,4,8,16}
            int S = 1;
            while (S < 16 && base * S * 2 <= 256) S *= 2;
            if (S == 1) {
                dim3 grid(gx, 2);
                layer_hmma<64><<<grid, 256, smem64>>>(cur_hi, cur_lo,
                    whi + (size_t)i * 256 * 512, wlo + (size_t)i * 256 * 512,
                    b + i * 256, ohi, olo, of, nullptr, Nin, Nout, fp32_in, 16);
            } else {
                dim3 grid(gx, 2, S);
                layer_hmma<64><<<grid, 256, smem64>>>(cur_hi, cur_lo,
                    whi + (size_t)i * 256 * 512, wlo + (size_t)i * 256 * 512,
                    b + i * 256, nullptr, nullptr, nullptr, gpart,
                    Nin, Nout, fp32_in, 16 / S);
                int work = (i == 15) ? 256 : 256 * (Nout >> 1);
                reduce_k<<<(work + 255) / 256, 256>>>(gpart, S, b + i * 256,
                                                      Nout, ohi, olo, of);
            }
        }
        cur_hi = (const void*)ohi;
        cur_lo = olo;
        fp32_in = 0;
        Nin = Nout;
    }
}